// round 6
// baseline (speedup 1.0000x reference)
#include <cuda_runtime.h>
#include <cstdint>

#define N_ATOMS_MAX 200000
#define N_IMAGES_MAX 128

// Per-atom scratch: [fx fy fz v00 v01 v02 v10 v11 v12 v20 v21 v22], 12 floats (48B, v4-aligned)
__device__ __align__(16) float g_scratch[(size_t)N_ATOMS_MAX * 12];
// Per-image virial accumulator, padded to 12 floats per image for v4 reds
__device__ __align__(16) float g_virial[N_IMAGES_MAX * 12];

__device__ __forceinline__ void red4(float* p, float a, float b, float c, float d) {
    asm volatile("red.global.add.v4.f32 [%0], {%1,%2,%3,%4};"
                 :: "l"(p), "f"(a), "f"(b), "f"(c), "f"(d) : "memory");
}

__global__ void zero_kernel() {
    size_t i = blockIdx.x * (size_t)blockDim.x + threadIdx.x;
    const float4 z = make_float4(0.f, 0.f, 0.f, 0.f);
    size_t n4 = (size_t)N_ATOMS_MAX * 3;   // scratch as float4 count
    if (i < n4) ((float4*)g_scratch)[i] = z;
    if (i < (size_t)N_IMAGES_MAX * 3) ((float4*)g_virial)[i] = z;
}

__global__ __launch_bounds__(256) void edge_kernel(
    const float* __restrict__ edge_diff,
    const float* __restrict__ dE,
    const int* __restrict__ edge_idx,
    int n_edges)
{
    int e = blockIdx.x * blockDim.x + threadIdx.x;
    if (e >= n_edges) return;

    float dx = edge_diff[3 * e + 0];
    float dy = edge_diff[3 * e + 1];
    float dz = edge_diff[3 * e + 2];
    float gx = dE[3 * e + 0];
    float gy = dE[3 * e + 1];
    float gz = dE[3 * e + 2];

    int2 idx = ((const int2*)edge_idx)[e];
    int i = idx.x;
    int j = idx.y;

    // i endpoint: force += g, virial += d (outer) g   -> 3 vectorized reds
    float* si = g_scratch + (size_t)i * 12;
    red4(si + 0, gx,        gy,        gz,        dx * gx);
    red4(si + 4, dx * gy,   dx * gz,   dy * gx,   dy * gy);
    red4(si + 8, dy * gz,   dz * gx,   dz * gy,   dz * gz);

    // j endpoint: force -= g                          -> 1 vectorized red (slot 3 is a no-op add)
    float* sj = g_scratch + (size_t)j * 12;
    red4(sj + 0, -gx, -gy, -gz, 0.f);
}

__global__ __launch_bounds__(256) void atom_kernel(
    const int* __restrict__ image_idx,
    float* __restrict__ out_forces,
    int n_atoms)
{
    int a = blockIdx.x * blockDim.x + threadIdx.x;
    if (a >= n_atoms) return;

    const float4* s = (const float4*)(g_scratch + (size_t)a * 12);
    float4 s0 = s[0];  // fx fy fz v0
    float4 s1 = s[1];  // v1 v2 v3 v4
    float4 s2 = s[2];  // v5 v6 v7 v8

    out_forces[3 * a + 0] = s0.x;
    out_forces[3 * a + 1] = s0.y;
    out_forces[3 * a + 2] = s0.z;

    int img = image_idx[a];
    float* v = g_virial + (size_t)img * 12;
    red4(v + 0, s0.w, s1.x, s1.y, s1.z);  // v0..v3
    red4(v + 4, s1.w, s2.x, s2.y, s2.z);  // v4..v7
    red4(v + 8, s2.w, 0.f, 0.f, 0.f);     // v8 (slots 9..11 are pad)
}

__global__ void finalize_kernel(
    const float* __restrict__ cell,
    float* __restrict__ out,
    int n_atoms, int n_images)
{
    int i = threadIdx.x;
    if (i >= n_images) return;

    const float* c = cell + i * 9;
    float a0 = c[0], a1 = c[1], a2 = c[2];
    float b0 = c[3], b1 = c[4], b2 = c[5];
    float c0 = c[6], c1 = c[7], c2 = c[8];
    // cross(b, c)
    float x0 = b1 * c2 - b2 * c1;
    float x1 = b2 * c0 - b0 * c2;
    float x2 = b0 * c1 - b1 * c0;
    float vol = a0 * x0 + a1 * x1 + a2 * x2;
    float inv = -1.0f / vol;

    const float* v = g_virial + (size_t)i * 12;
    float* vir_out    = out + (size_t)n_atoms * 3 + (size_t)i * 9;
    float* stress_out = out + (size_t)n_atoms * 3 + (size_t)n_images * 9 + (size_t)i * 9;
#pragma unroll
    for (int k = 0; k < 9; k++) {
        float val = v[k];
        vir_out[k] = val;
        stress_out[k] = val * inv;
    }
}

extern "C" void kernel_launch(void* const* d_in, const int* in_sizes, int n_in,
                              void* d_out, int out_size)
{
    const float* edge_diff = (const float*)d_in[0];
    const float* dE        = (const float*)d_in[1];
    const float* cell      = (const float*)d_in[2];
    const int*   edge_idx  = (const int*)d_in[3];
    const int*   image_idx = (const int*)d_in[4];

    int n_edges  = in_sizes[0] / 3;
    int n_atoms  = in_sizes[4];
    int n_images = in_sizes[2] / 9;
    float* out = (float*)d_out;

    int zthreads = 256;
    int zblocks = ((N_ATOMS_MAX * 3) + zthreads - 1) / zthreads;
    zero_kernel<<<zblocks, zthreads>>>();

    edge_kernel<<<(n_edges + 255) / 256, 256>>>(edge_diff, dE, edge_idx, n_edges);

    atom_kernel<<<(n_atoms + 255) / 256, 256>>>(image_idx, out, n_atoms);

    finalize_kernel<<<1, 128>>>(cell, out, n_atoms, n_images);
}

// round 7
// speedup vs baseline: 1.0066x; 1.0066x over previous
#include <cuda_runtime.h>
#include <cstdint>

#define N_ATOMS_MAX 200000
#define N_IMAGES_MAX 128

// Per-atom scratch row: [fx fy fz v00 v01 v02 v10 v11 v12 v20 v21 v22] (12 floats, 48B, 16B-aligned)
__device__ __align__(16) float g_scratch[(size_t)N_ATOMS_MAX * 12];
// Per-image virial accumulator, 12 floats per image (9 used + pad) for v4 reds
__device__ __align__(16) float g_virial[N_IMAGES_MAX * 12];
__device__ int g_counter;

__device__ __forceinline__ void red4(float* p, float a, float b, float c, float d) {
    asm volatile("red.global.add.v4.f32 [%0], {%1,%2,%3,%4};"
                 :: "l"(p), "f"(a), "f"(b), "f"(c), "f"(d) : "memory");
}

__global__ void zero_kernel() {
    size_t i = blockIdx.x * (size_t)blockDim.x + threadIdx.x;
    const float4 z = make_float4(0.f, 0.f, 0.f, 0.f);
    if (i < (size_t)N_ATOMS_MAX * 3) ((float4*)g_scratch)[i] = z;
    if (i < (size_t)N_IMAGES_MAX * 3) ((float4*)g_virial)[i] = z;
    if (i == 0) g_counter = 0;
}

__device__ __forceinline__ void process_edge(
    float dx, float dy, float dz,
    float gx, float gy, float gz,
    int i, int j)
{
    // i endpoint: 3 force comps + 9 virial comps = exactly 3 v4 reds
    float* si = g_scratch + (size_t)i * 12;
    red4(si + 0, gx,      gy,      gz,      dx * gx);
    red4(si + 4, dx * gy, dx * gz, dy * gx, dy * gy);
    red4(si + 8, dy * gz, dz * gx, dz * gy, dz * gz);
    // j endpoint: force -= g
    float* sj = g_scratch + (size_t)j * 12;
    red4(sj + 0, -gx, -gy, -gz, 0.f);
}

__global__ __launch_bounds__(256) void edge_kernel(
    const float* __restrict__ edge_diff,
    const float* __restrict__ dE,
    const int* __restrict__ edge_idx,
    int n_edges)
{
    int q = blockIdx.x * blockDim.x + threadIdx.x;   // quad index: 4 edges per thread
    int base = 4 * q;
    if (base >= n_edges) return;

    if (base + 3 < n_edges) {
        // Fully vectorized path: 3x LDG.128 per array, 2x int4 for indices
        const float4* diff4 = (const float4*)edge_diff;
        const float4* dE4   = (const float4*)dE;
        const int4*   idx4  = (const int4*)edge_idx;

        float4 d0 = diff4[3 * q + 0];
        float4 d1 = diff4[3 * q + 1];
        float4 d2 = diff4[3 * q + 2];
        float4 g0 = dE4[3 * q + 0];
        float4 g1 = dE4[3 * q + 1];
        float4 g2 = dE4[3 * q + 2];
        int4 i0 = idx4[2 * q + 0];
        int4 i1 = idx4[2 * q + 1];

        process_edge(d0.x, d0.y, d0.z, g0.x, g0.y, g0.z, i0.x, i0.y);
        process_edge(d0.w, d1.x, d1.y, g0.w, g1.x, g1.y, i0.z, i0.w);
        process_edge(d1.z, d1.w, d2.x, g1.z, g1.w, g2.x, i1.x, i1.y);
        process_edge(d2.y, d2.z, d2.w, g2.y, g2.z, g2.w, i1.z, i1.w);
    } else {
        // Scalar tail
        for (int e = base; e < n_edges; e++) {
            process_edge(edge_diff[3 * e + 0], edge_diff[3 * e + 1], edge_diff[3 * e + 2],
                         dE[3 * e + 0], dE[3 * e + 1], dE[3 * e + 2],
                         edge_idx[2 * e + 0], edge_idx[2 * e + 1]);
        }
    }
}

__global__ __launch_bounds__(256) void atom_kernel(
    const int* __restrict__ image_idx,
    const float* __restrict__ cell,
    float* __restrict__ out,
    int n_atoms, int n_images)
{
    int a = blockIdx.x * blockDim.x + threadIdx.x;
    if (a < n_atoms) {
        const float4* s = (const float4*)(g_scratch + (size_t)a * 12);
        float4 s0 = s[0];  // fx fy fz v0
        float4 s1 = s[1];  // v1 v2 v3 v4
        float4 s2 = s[2];  // v5 v6 v7 v8

        out[3 * a + 0] = s0.x;
        out[3 * a + 1] = s0.y;
        out[3 * a + 2] = s0.z;

        int img = image_idx[a];
        float* v = g_virial + (size_t)img * 12;
        red4(v + 0, s0.w, s1.x, s1.y, s1.z);
        red4(v + 4, s1.w, s2.x, s2.y, s2.z);
        red4(v + 8, s2.w, 0.f, 0.f, 0.f);
    }

    // Last-block-done: fold finalize into this kernel (saves one graph launch)
    __threadfence();
    __shared__ int is_last;
    if (threadIdx.x == 0) {
        int old = atomicAdd(&g_counter, 1);
        is_last = (old == (int)gridDim.x - 1) ? 1 : 0;
    }
    __syncthreads();
    if (is_last) {
        __threadfence();   // acquire side: make all blocks' reds visible
        int i = threadIdx.x;
        if (i < n_images) {
            const float* c = cell + i * 9;
            float a0 = c[0], a1 = c[1], a2 = c[2];
            float b0 = c[3], b1 = c[4], b2 = c[5];
            float c0 = c[6], c1 = c[7], c2 = c[8];
            float x0 = b1 * c2 - b2 * c1;
            float x1 = b2 * c0 - b0 * c2;
            float x2 = b0 * c1 - b1 * c0;
            float vol = a0 * x0 + a1 * x1 + a2 * x2;
            float inv = -1.0f / vol;

            const float* v = g_virial + (size_t)i * 12;
            float* vir_out    = out + (size_t)n_atoms * 3 + (size_t)i * 9;
            float* stress_out = out + (size_t)n_atoms * 3 + (size_t)n_images * 9 + (size_t)i * 9;
#pragma unroll
            for (int k = 0; k < 9; k++) {
                float val = v[k];
                vir_out[k] = val;
                stress_out[k] = val * inv;
            }
        }
    }
}

extern "C" void kernel_launch(void* const* d_in, const int* in_sizes, int n_in,
                              void* d_out, int out_size)
{
    const float* edge_diff = (const float*)d_in[0];
    const float* dE        = (const float*)d_in[1];
    const float* cell      = (const float*)d_in[2];
    const int*   edge_idx  = (const int*)d_in[3];
    const int*   image_idx = (const int*)d_in[4];

    int n_edges  = in_sizes[0] / 3;
    int n_atoms  = in_sizes[4];
    int n_images = in_sizes[2] / 9;
    float* out = (float*)d_out;

    int zthreads = 256;
    int zblocks = ((N_ATOMS_MAX * 3) + zthreads - 1) / zthreads;
    zero_kernel<<<zblocks, zthreads>>>();

    int n_quads = (n_edges + 3) / 4;
    edge_kernel<<<(n_quads + 255) / 256, 256>>>(edge_diff, dE, edge_idx, n_edges);

    atom_kernel<<<(n_atoms + 255) / 256, 256>>>(image_idx, cell, out, n_atoms, n_images);
}

// round 8
// speedup vs baseline: 1.3630x; 1.3541x over previous
#include <cuda_runtime.h>
#include <cstdint>

#define N_ATOMS_MAX 200000
#define N_IMAGES_MAX 128

// Zero-initialized at module load. Every run restores the all-zero invariant:
//  - atom_kernel writes zeros back to each scratch row it consumes
//  - the last block re-zeros g_virial and resets g_counter
__device__ __align__(16) float g_scratch[(size_t)N_ATOMS_MAX * 12];
__device__ __align__(16) float g_virial[N_IMAGES_MAX * 12];
__device__ int g_counter;   // zero-init, reset by last block each run

__device__ __forceinline__ void red4(float* p, float a, float b, float c, float d) {
    asm volatile("red.global.add.v4.f32 [%0], {%1,%2,%3,%4};"
                 :: "l"(p), "f"(a), "f"(b), "f"(c), "f"(d) : "memory");
}

__device__ __forceinline__ void process_edge(
    float dx, float dy, float dz,
    float gx, float gy, float gz,
    int i, int j)
{
    // i endpoint: 3 force comps + 9 virial comps packed into exactly 3 v4 reds
    float* si = g_scratch + (size_t)i * 12;
    red4(si + 0, gx,      gy,      gz,      dx * gx);
    red4(si + 4, dx * gy, dx * gz, dy * gx, dy * gy);
    red4(si + 8, dy * gz, dz * gx, dz * gy, dz * gz);
    // j endpoint: force -= g
    float* sj = g_scratch + (size_t)j * 12;
    red4(sj + 0, -gx, -gy, -gz, 0.f);
}

__global__ __launch_bounds__(256) void edge_kernel(
    const float* __restrict__ edge_diff,
    const float* __restrict__ dE,
    const int* __restrict__ edge_idx,
    int n_edges)
{
    int q = blockIdx.x * blockDim.x + threadIdx.x;   // 4 edges per thread
    int base = 4 * q;
    if (base >= n_edges) return;

    if (base + 3 < n_edges) {
        const float4* diff4 = (const float4*)edge_diff;
        const float4* dE4   = (const float4*)dE;
        const int4*   idx4  = (const int4*)edge_idx;

        float4 d0 = diff4[3 * q + 0];
        float4 d1 = diff4[3 * q + 1];
        float4 d2 = diff4[3 * q + 2];
        float4 g0 = dE4[3 * q + 0];
        float4 g1 = dE4[3 * q + 1];
        float4 g2 = dE4[3 * q + 2];
        int4 i0 = idx4[2 * q + 0];
        int4 i1 = idx4[2 * q + 1];

        process_edge(d0.x, d0.y, d0.z, g0.x, g0.y, g0.z, i0.x, i0.y);
        process_edge(d0.w, d1.x, d1.y, g0.w, g1.x, g1.y, i0.z, i0.w);
        process_edge(d1.z, d1.w, d2.x, g1.z, g1.w, g2.x, i1.x, i1.y);
        process_edge(d2.y, d2.z, d2.w, g2.y, g2.z, g2.w, i1.z, i1.w);
    } else {
        for (int e = base; e < n_edges; e++) {
            process_edge(edge_diff[3 * e + 0], edge_diff[3 * e + 1], edge_diff[3 * e + 2],
                         dE[3 * e + 0], dE[3 * e + 1], dE[3 * e + 2],
                         edge_idx[2 * e + 0], edge_idx[2 * e + 1]);
        }
    }
}

__global__ __launch_bounds__(256) void atom_kernel(
    const int* __restrict__ image_idx,
    const float* __restrict__ cell,
    float* __restrict__ out,
    int n_atoms, int n_images)
{
    int a = blockIdx.x * blockDim.x + threadIdx.x;
    const float4 z4 = make_float4(0.f, 0.f, 0.f, 0.f);

    int img = -1;
    float v[9];
#pragma unroll
    for (int k = 0; k < 9; k++) v[k] = 0.f;

    if (a < n_atoms) {
        float4* s = (float4*)(g_scratch + (size_t)a * 12);
        float4 s0 = s[0];  // fx fy fz v0
        float4 s1 = s[1];  // v1 v2 v3 v4
        float4 s2 = s[2];  // v5 v6 v7 v8

        // restore zero invariant for next replay
        s[0] = z4; s[1] = z4; s[2] = z4;

        out[3 * a + 0] = s0.x;
        out[3 * a + 1] = s0.y;
        out[3 * a + 2] = s0.z;

        img = image_idx[a];
        v[0] = s0.w; v[1] = s1.x; v[2] = s1.y; v[3] = s1.z;
        v[4] = s1.w; v[5] = s2.x; v[6] = s2.y; v[7] = s2.z; v[8] = s2.w;
    }

    // image_idx is sorted -> almost every warp is image-uniform: aggregate in-warp
    int lane = threadIdx.x & 31;
    int img0 = __shfl_sync(0xFFFFFFFFu, img, 0);
    bool uniform = __all_sync(0xFFFFFFFFu, img == img0) && (img0 >= 0);

    if (uniform) {
#pragma unroll
        for (int k = 0; k < 9; k++) {
#pragma unroll
            for (int off = 16; off > 0; off >>= 1)
                v[k] += __shfl_xor_sync(0xFFFFFFFFu, v[k], off);
        }
        if (lane == 0) {
            float* g = g_virial + (size_t)img0 * 12;
            red4(g + 0, v[0], v[1], v[2], v[3]);
            red4(g + 4, v[4], v[5], v[6], v[7]);
            red4(g + 8, v[8], 0.f, 0.f, 0.f);
        }
    } else if (img >= 0) {
        float* g = g_virial + (size_t)img * 12;
        red4(g + 0, v[0], v[1], v[2], v[3]);
        red4(g + 4, v[4], v[5], v[6], v[7]);
        red4(g + 8, v[8], 0.f, 0.f, 0.f);
    }

    // Last-block-done: finalize virial -> out, compute stress, restore invariants
    __threadfence();
    __shared__ int is_last;
    if (threadIdx.x == 0) {
        int old = atomicAdd(&g_counter, 1);
        is_last = (old == (int)gridDim.x - 1) ? 1 : 0;
    }
    __syncthreads();
    if (is_last) {
        __threadfence();   // acquire: make all blocks' reds visible
        int i = threadIdx.x;
        if (i < n_images) {
            const float* c = cell + i * 9;
            float a0 = c[0], a1 = c[1], a2 = c[2];
            float b0 = c[3], b1 = c[4], b2 = c[5];
            float c0 = c[6], c1 = c[7], c2 = c[8];
            float x0 = b1 * c2 - b2 * c1;
            float x1 = b2 * c0 - b0 * c2;
            float x2 = b0 * c1 - b1 * c0;
            float vol = a0 * x0 + a1 * x1 + a2 * x2;
            float inv = -1.0f / vol;

            float* gv = g_virial + (size_t)i * 12;
            float* vir_out    = out + (size_t)n_atoms * 3 + (size_t)i * 9;
            float* stress_out = out + (size_t)n_atoms * 3 + (size_t)n_images * 9 + (size_t)i * 9;
            float vv[9];
#pragma unroll
            for (int k = 0; k < 9; k++) vv[k] = gv[k];
#pragma unroll
            for (int k = 0; k < 9; k++) {
                vir_out[k] = vv[k];
                stress_out[k] = vv[k] * inv;
            }
            // restore zero invariant
            float4* gv4 = (float4*)gv;
            gv4[0] = z4; gv4[1] = z4; gv4[2] = z4;
        }
        if (threadIdx.x == 0) g_counter = 0;
    }
}

extern "C" void kernel_launch(void* const* d_in, const int* in_sizes, int n_in,
                              void* d_out, int out_size)
{
    const float* edge_diff = (const float*)d_in[0];
    const float* dE        = (const float*)d_in[1];
    const float* cell      = (const float*)d_in[2];
    const int*   edge_idx  = (const int*)d_in[3];
    const int*   image_idx = (const int*)d_in[4];

    int n_edges  = in_sizes[0] / 3;
    int n_atoms  = in_sizes[4];
    int n_images = in_sizes[2] / 9;
    float* out = (float*)d_out;

    int n_quads = (n_edges + 3) / 4;
    edge_kernel<<<(n_quads + 255) / 256, 256>>>(edge_diff, dE, edge_idx, n_edges);

    atom_kernel<<<(n_atoms + 255) / 256, 256>>>(image_idx, cell, out, n_atoms, n_images);
}